// round 10
// baseline (speedup 1.0000x reference)
#include <cuda_runtime.h>
#include <cuda_bf16.h>
#include <cstdint>

// ---------------- problem constants ----------------
#define MAXN 50000

// ---------------- device scratch ----------------
__device__ float g_sums[MAXN * 256];
__device__ int   g_cnt [MAXN];
__device__ int   g_idx64;
// weight blobs: per layer 8 chunks (k=32) x [hi 20480 | lo 20480] = 327680 B
// layout inside half-chunk: [n (256)][stride 80 B], element (n, kk) at n*80 + kk*2
__device__ __align__(16) unsigned char g_w1blob[8 * 40960];
__device__ __align__(16) unsigned char g_w2blob[8 * 40960];

// ---------------- smem layout (bytes) ----------------
#define A_STRIDE_B 528              // 264 halves per row (256 + 8 pad)
#define SA_HI  0
#define SA_LO  67584                // 128 * 528
#define SB0    135168
#define SB1    176128               // SB0 + 40960
#define SBIA   217088               // b1a, 256 floats
#define SBIB   218112               // b1b, 256 floats
#define SROW   219136               // 128 ints
#define SCOL   219648
#define EDGE_SMEM 220160

#define CHUNK_BYTES 40960
#define CHUNK_HALF  20480

// ---------------- helpers ----------------
__device__ __forceinline__ uint32_t smem_u32(const void* p) {
    uint32_t a;
    asm("{ .reg .u64 t; cvta.to.shared.u64 t, %1; cvt.u32.u64 %0, t; }" : "=r"(a) : "l"(p));
    return a;
}
__device__ __forceinline__ void cp16(uint32_t saddr, const void* gaddr) {
    asm volatile("cp.async.cg.shared.global [%0], [%1], 16;" :: "r"(saddr), "l"(gaddr));
}
#define CP_COMMIT() asm volatile("cp.async.commit_group;")
#define CP_WAIT1()  asm volatile("cp.async.wait_group 1;")

__device__ __forceinline__ void red_add_v2(float* p, float a, float b) {
    asm volatile("red.global.add.v2.f32 [%0], {%1, %2};" :: "l"(p), "f"(a), "f"(b) : "memory");
}
__device__ __forceinline__ void mma16816(float* c, const uint32_t* a, const uint32_t* b) {
    asm volatile(
        "mma.sync.aligned.m16n8k16.row.col.f32.bf16.bf16.f32 "
        "{%0,%1,%2,%3}, {%4,%5,%6,%7}, {%8,%9}, {%0,%1,%2,%3};"
        : "+f"(c[0]), "+f"(c[1]), "+f"(c[2]), "+f"(c[3])
        : "r"(a[0]), "r"(a[1]), "r"(a[2]), "r"(a[3]), "r"(b[0]), "r"(b[1]));
}
__device__ __forceinline__ void ldm_x4(uint32_t addr, uint32_t* r) {
    asm volatile("ldmatrix.sync.aligned.m8n8.x4.shared.b16 {%0,%1,%2,%3}, [%4];"
                 : "=r"(r[0]), "=r"(r[1]), "=r"(r[2]), "=r"(r[3]) : "r"(addr));
}
// split two fp32 into packed bf16x2 (hi) and bf16x2 (lo residual)
__device__ __forceinline__ void split2(float v0, float v1, uint32_t& hi, uint32_t& lo) {
    __nv_bfloat16 h0 = __float2bfloat16(v0), h1 = __float2bfloat16(v1);
    __nv_bfloat162 hh{h0, h1};
    __nv_bfloat162 ll{__float2bfloat16(v0 - __bfloat162float(h0)),
                      __float2bfloat16(v1 - __bfloat162float(h1))};
    hi = *(uint32_t*)&hh;
    lo = *(uint32_t*)&ll;
}

// ======================================================================
// detect index dtype
// ======================================================================
__global__ void detect_idx_kernel(const int* __restrict__ ei_raw) {
    __shared__ int any_nonzero;
    if (threadIdx.x == 0) any_nonzero = 0;
    __syncthreads();
    for (int i = threadIdx.x; i < 1024; i += blockDim.x)
        if (ei_raw[2 * i + 1] != 0) any_nonzero = 1;
    __syncthreads();
    if (threadIdx.x == 0) g_idx64 = (any_nonzero == 0) ? 1 : 0;
}
__device__ __forceinline__ int load_idx(const void* ei, long long pos, int nmax) {
    int v = g_idx64 ? (int)((const long long*)ei)[pos] : ((const int*)ei)[pos];
    return min(max(v, 0), nmax - 1);
}

// ======================================================================
// zero scratch
// ======================================================================
__global__ void zero_kernel(int n_nodes) {
    int tid = blockIdx.x * blockDim.x + threadIdx.x;
    int stride = gridDim.x * blockDim.x;
    int tot4 = n_nodes * 64;
    float4* s4 = (float4*)g_sums;
    float4 z = make_float4(0.f, 0.f, 0.f, 0.f);
    for (int i = tid; i < tot4; i += stride) s4[i] = z;
    for (int i = tid; i < n_nodes; i += stride) g_cnt[i] = 0;
}

// ======================================================================
// prep: w [256 K][256 N] fp32 -> blob chunks (B^T, padded rows)
// ======================================================================
__global__ void prep_weights_kernel(const float* __restrict__ w, unsigned char* __restrict__ blob) {
    int idx = blockIdx.x * blockDim.x + threadIdx.x;
    if (idx >= 256 * 256) return;
    int k = idx >> 8, n = idx & 255;
    float v = w[idx];
    __nv_bfloat16 hi = __float2bfloat16(v);
    __nv_bfloat16 lo = __float2bfloat16(v - __bfloat162float(hi));
    int ch = k >> 5, kk = k & 31;
    unsigned char* base = blob + ch * CHUNK_BYTES + n * 80 + kk * 2;
    *(__nv_bfloat16*)(base)              = hi;
    *(__nv_bfloat16*)(base + CHUNK_HALF) = lo;
}

// ======================================================================
// edge kernel: HMMA bf16-3split + ldmatrix, 128 edges / CTA, 512 threads
// ======================================================================
__global__ __launch_bounds__(512, 1)
void edge_mma_kernel(const float* __restrict__ x,
                     const void* __restrict__ edge_index,
                     const float* __restrict__ edge_attr,
                     const float* __restrict__ b1a, const float* __restrict__ b1b,
                     int E, int N)
{
    extern __shared__ __align__(16) unsigned char smem[];
    const uint32_t sbase = smem_u32(smem);
    const int tid  = threadIdx.x;
    const int lane = tid & 31;
    const int w    = tid >> 5;          // 16 warps
    const int g    = lane >> 2;         // 0..7
    const int tg   = lane & 3;          // 0..3
    const int mb   = (w >> 2) * 32;     // warp M base (0/32/64/96)
    const int nb   = (w & 3) * 64;      // warp N base (0/64/128/192)
    // ldmatrix lane mapping
    const int sel  = lane >> 3;         // 0..3 (which 8x8 matrix)
    const int rin  = lane & 7;          // row within matrix

    const int e0 = blockIdx.x * 128;
    const int ecnt = min(128, E - e0);
    int*   srow = (int*)(smem + SROW);
    int*   scol = (int*)(smem + SCOL);
    float* sba  = (float*)(smem + SBIA);
    float* sbb  = (float*)(smem + SBIB);

    if (tid < 128) {
        int r = -1, c = -1;
        if (tid < ecnt) {
            r = load_idx(edge_index, (long long)(e0 + tid), N);
            c = load_idx(edge_index, (long long)E + e0 + tid, N);
            atomicAdd(&g_cnt[c], 1);
        }
        srow[tid] = r;
        scol[tid] = c;
    }
    if (tid < 256) {
        sba[tid] = b1a[tid];
        sbb[tid] = b1b[tid];
    }
    __syncthreads();

    // ---- gather inputs, split, store to A_hi/A_lo (padded rows) ----
    for (int idx = tid; idx < 128 * 32; idx += 512) {       // x : k = c4*4
        int e = idx >> 5, c4 = idx & 31;
        float4 v = make_float4(0.f, 0.f, 0.f, 0.f);
        if (e < ecnt) v = *(const float4*)(x + (long long)srow[e] * 128 + c4 * 4);
        uint32_t h0, l0, h1, l1;
        split2(v.x, v.y, h0, l0);
        split2(v.z, v.w, h1, l1);
        uint32_t off = (uint32_t)e * A_STRIDE_B + (uint32_t)c4 * 8;
        *(uint2*)(smem + SA_HI + off) = make_uint2(h0, h1);
        *(uint2*)(smem + SA_LO + off) = make_uint2(l0, l1);
    }
    for (int idx = tid; idx < 128 * 32; idx += 512) {       // edge_attr : k = 128 + c4*4
        int e = idx >> 5, c4 = idx & 31;
        float4 v = make_float4(0.f, 0.f, 0.f, 0.f);
        if (e < ecnt) v = *(const float4*)(edge_attr + (long long)(e0 + e) * 128 + c4 * 4);
        uint32_t h0, l0, h1, l1;
        split2(v.x, v.y, h0, l0);
        split2(v.z, v.w, h1, l1);
        uint32_t off = (uint32_t)e * A_STRIDE_B + 256u + (uint32_t)c4 * 8;
        *(uint2*)(smem + SA_HI + off) = make_uint2(h0, h1);
        *(uint2*)(smem + SA_LO + off) = make_uint2(l0, l1);
    }
    __syncthreads();

    float acc[2][8][4];
    #pragma unroll
    for (int mt = 0; mt < 2; mt++)
        #pragma unroll
        for (int nt = 0; nt < 8; nt++)
            #pragma unroll
            for (int i = 0; i < 4; i++) acc[mt][nt][i] = 0.f;

    // chunk copy: 2560 x 16B with 512 threads (5 each)
    #define CP_CHUNK(GSRC, SDST)                                           \
        {                                                                  \
            const unsigned char* _g = (GSRC);                              \
            uint32_t _s = sbase + (SDST);                                  \
            _Pragma("unroll")                                              \
            for (int _j = 0; _j < 5; _j++)                                 \
                cp16(_s + (tid + _j * 512) * 16, _g + (tid + _j * 512) * 16); \
        }

    // one k16-step of the 3-split GEMM, fragments via ldmatrix.x4
    // A: matrices {rows 0-7 | rows 8-15 | k+8 rows 0-7 | k+8 rows 8-15}
    // B: matrices {hi k0-7 | hi k8-15 | lo k0-7 | lo k8-15} for one nt
    #define GEMM_KSTEP(K0, KC, SBCUR)                                      \
        {                                                                  \
            uint32_t ahi[2][4], alo[2][4];                                 \
            _Pragma("unroll")                                              \
            for (int mt = 0; mt < 2; mt++) {                               \
                uint32_t row = (uint32_t)(mb + mt * 16 + ((sel & 1) << 3) + rin); \
                uint32_t byt = row * A_STRIDE_B + (uint32_t)(K0) * 2 + ((sel >> 1) << 4); \
                ldm_x4(sbase + SA_HI + byt, ahi[mt]);                      \
                ldm_x4(sbase + SA_LO + byt, alo[mt]);                      \
            }                                                              \
            _Pragma("unroll")                                              \
            for (int nt = 0; nt < 8; nt++) {                               \
                uint32_t n = (uint32_t)(nb + nt * 8 + rin);                \
                uint32_t byt = n * 80u + (uint32_t)(KC) * 2                \
                             + ((sel & 1) << 4) + (sel >> 1) * CHUNK_HALF; \
                uint32_t b[4];                                             \
                ldm_x4(sbase + (SBCUR) + byt, b);                          \
                _Pragma("unroll")                                          \
                for (int mt = 0; mt < 2; mt++) {                           \
                    mma16816(acc[mt][nt], ahi[mt], b);                     \
                    mma16816(acc[mt][nt], ahi[mt], b + 2);                 \
                    mma16816(acc[mt][nt], alo[mt], b);                     \
                }                                                          \
            }                                                              \
        }

    // ---- GEMM1: [x|ea] (128x256) @ w1a -> acc ----
    CP_CHUNK(g_w1blob, SB0);
    CP_COMMIT();
    for (int ch = 0; ch < 8; ch++) {
        if (ch < 7) { CP_CHUNK(g_w1blob + (ch + 1) * CHUNK_BYTES, ((ch + 1) & 1) ? SB1 : SB0); }
        else        { CP_CHUNK(g_w2blob, SB0); }    // prefetch GEMM2 chunk 0
        CP_COMMIT();
        CP_WAIT1();
        __syncthreads();
        uint32_t sb = (ch & 1) ? SB1 : SB0;
        GEMM_KSTEP(ch * 32,      0,  sb);
        GEMM_KSTEP(ch * 32 + 16, 16, sb);
        __syncthreads();
    }

    // ---- layer-1 epilogue: bias + ELU + re-split -> overwrite A ----
    {
        #pragma unroll
        for (int mt = 0; mt < 2; mt++) {
            uint32_t r0 = (uint32_t)(mb + mt * 16 + g);
            #pragma unroll
            for (int nt = 0; nt < 8; nt++) {
                int cb = nb + nt * 8 + tg * 2;
                float b0 = sba[cb], b1 = sba[cb + 1];
                float v00 = acc[mt][nt][0] + b0, v01 = acc[mt][nt][1] + b1;
                float v10 = acc[mt][nt][2] + b0, v11 = acc[mt][nt][3] + b1;
                v00 = (v00 > 0.f) ? v00 : expm1f(v00);
                v01 = (v01 > 0.f) ? v01 : expm1f(v01);
                v10 = (v10 > 0.f) ? v10 : expm1f(v10);
                v11 = (v11 > 0.f) ? v11 : expm1f(v11);
                uint32_t hi, lo;
                uint32_t o = r0 * A_STRIDE_B + (uint32_t)cb * 2;
                split2(v00, v01, hi, lo);
                *(uint32_t*)(smem + SA_HI + o) = hi;
                *(uint32_t*)(smem + SA_LO + o) = lo;
                o += 8 * A_STRIDE_B;
                split2(v10, v11, hi, lo);
                *(uint32_t*)(smem + SA_HI + o) = hi;
                *(uint32_t*)(smem + SA_LO + o) = lo;
                acc[mt][nt][0] = 0.f; acc[mt][nt][1] = 0.f;
                acc[mt][nt][2] = 0.f; acc[mt][nt][3] = 0.f;
            }
        }
    }
    __syncthreads();

    // ---- GEMM2: elu(H1) (128x256) @ w1b -> acc ----
    for (int ch = 0; ch < 8; ch++) {
        if (ch < 7) { CP_CHUNK(g_w2blob + (ch + 1) * CHUNK_BYTES, ((ch + 1) & 1) ? SB1 : SB0); }
        CP_COMMIT();
        CP_WAIT1();
        __syncthreads();
        uint32_t sb = (ch & 1) ? SB1 : SB0;
        GEMM_KSTEP(ch * 32,      0,  sb);
        GEMM_KSTEP(ch * 32 + 16, 16, sb);
        __syncthreads();
    }

    // ---- scatter epilogue: + b1b, red.global.add.v2 into g_sums ----
    {
        #pragma unroll
        for (int mt = 0; mt < 2; mt++) {
            int er0 = mb + mt * 16 + g;
            int c0 = scol[er0];
            int c1 = scol[er0 + 8];
            float* p0 = (c0 >= 0) ? (g_sums + (long long)c0 * 256) : nullptr;
            float* p1 = (c1 >= 0) ? (g_sums + (long long)c1 * 256) : nullptr;
            #pragma unroll
            for (int nt = 0; nt < 8; nt++) {
                int cb = nb + nt * 8 + tg * 2;
                float b0 = sbb[cb], b1 = sbb[cb + 1];
                if (p0) red_add_v2(p0 + cb, acc[mt][nt][0] + b0, acc[mt][nt][1] + b1);
                if (p1) red_add_v2(p1 + cb, acc[mt][nt][2] + b0, acc[mt][nt][3] + b1);
            }
        }
    }
}

// ======================================================================
// node MLP (scalar fp32)
// ======================================================================
__global__ __launch_bounds__(256)
void node_mlp_kernel(const float* __restrict__ x,
                     const float* __restrict__ w2a, const float* __restrict__ b2a,
                     const float* __restrict__ w2b, const float* __restrict__ b2b,
                     float* __restrict__ out, int N)
{
    extern __shared__ float smemf[];
    float* buf  = smemf;             // 64*384
    float* wbuf = smemf + 64 * 384;  // 16*256
    __shared__ float sInv[64];

    const int tid = threadIdx.x;
    const int er  = tid >> 5;
    const int cg  = tid & 31;
    const int n0  = blockIdx.x * 64;
    const int ncnt = min(64, N - n0);

    if (tid < 64) {
        float inv = 0.f;
        if (tid < ncnt) inv = 1.0f / (float)max(g_cnt[n0 + tid], 1);
        sInv[tid] = inv;
    }
    __syncthreads();

    for (int idx = tid; idx < 64 * 32; idx += 256) {
        int e = idx >> 5, c4 = idx & 31;
        float4 v = make_float4(0.f, 0.f, 0.f, 0.f);
        if (e < ncnt) v = *(const float4*)(x + (long long)(n0 + e) * 128 + c4 * 4);
        *(float4*)(buf + e * 384 + c4 * 4) = v;
    }
    for (int idx = tid; idx < 64 * 64; idx += 256) {
        int e = idx >> 6, c4 = idx & 63;
        float4 v = make_float4(0.f, 0.f, 0.f, 0.f);
        if (e < ncnt) {
            v = *(const float4*)(g_sums + (long long)(n0 + e) * 256 + c4 * 4);
            float inv = sInv[e];
            v.x *= inv; v.y *= inv; v.z *= inv; v.w *= inv;
        }
        *(float4*)(buf + e * 384 + 128 + c4 * 4) = v;
    }

    float acc[8][8];
    #pragma unroll
    for (int i = 0; i < 8; i++)
        #pragma unroll
        for (int j = 0; j < 8; j++) acc[i][j] = 0.f;

    for (int k0 = 0; k0 < 384; k0 += 16) {
        __syncthreads();
        const float4* wsrc = (const float4*)(w2a + k0 * 256);
        float4* wd = (float4*)wbuf;
        #pragma unroll
        for (int t = 0; t < 4; t++) wd[tid + t * 256] = wsrc[tid + t * 256];
        __syncthreads();
        #pragma unroll
        for (int kk = 0; kk < 16; kk++) {
            float a[8];
            #pragma unroll
            for (int i = 0; i < 8; i++) a[i] = buf[(er * 8 + i) * 384 + k0 + kk];
            float4 b0 = *(float4*)(wbuf + kk * 256 + cg * 8);
            float4 b1 = *(float4*)(wbuf + kk * 256 + cg * 8 + 4);
            float b[8] = {b0.x, b0.y, b0.z, b0.w, b1.x, b1.y, b1.z, b1.w};
            #pragma unroll
            for (int i = 0; i < 8; i++)
                #pragma unroll
                for (int j = 0; j < 8; j++) acc[i][j] = fmaf(a[i], b[j], acc[i][j]);
        }
    }

    __syncthreads();
    {
        float bj[8];
        #pragma unroll
        for (int j = 0; j < 8; j++) bj[j] = b2a[cg * 8 + j];
        #pragma unroll
        for (int i = 0; i < 8; i++) {
            float vv[8];
            #pragma unroll
            for (int j = 0; j < 8; j++) {
                float v = acc[i][j] + bj[j];
                vv[j] = (v > 0.f) ? v : expm1f(v);
                acc[i][j] = 0.f;
            }
            *(float4*)(buf + (er * 8 + i) * 256 + cg * 8)     = make_float4(vv[0], vv[1], vv[2], vv[3]);
            *(float4*)(buf + (er * 8 + i) * 256 + cg * 8 + 4) = make_float4(vv[4], vv[5], vv[6], vv[7]);
        }
    }

    for (int k0 = 0; k0 < 256; k0 += 16) {
        __syncthreads();
        const float4* wsrc = (const float4*)(w2b + k0 * 256);
        float4* wd = (float4*)wbuf;
        #pragma unroll
        for (int t = 0; t < 4; t++) wd[tid + t * 256] = wsrc[tid + t * 256];
        __syncthreads();
        #pragma unroll
        for (int kk = 0; kk < 16; kk++) {
            float a[8];
            #pragma unroll
            for (int i = 0; i < 8; i++) a[i] = buf[(er * 8 + i) * 256 + k0 + kk];
            float4 b0 = *(float4*)(wbuf + kk * 256 + cg * 8);
            float4 b1 = *(float4*)(wbuf + kk * 256 + cg * 8 + 4);
            float b[8] = {b0.x, b0.y, b0.z, b0.w, b1.x, b1.y, b1.z, b1.w};
            #pragma unroll
            for (int i = 0; i < 8; i++)
                #pragma unroll
                for (int j = 0; j < 8; j++) acc[i][j] = fmaf(a[i], b[j], acc[i][j]);
        }
    }

    {
        float bj[8];
        #pragma unroll
        for (int j = 0; j < 8; j++) bj[j] = b2b[cg * 8 + j];
        #pragma unroll
        for (int i = 0; i < 8; i++) {
            int n = n0 + er * 8 + i;
            if (n < N) {
                float vv[8];
                #pragma unroll
                for (int j = 0; j < 8; j++) vv[j] = acc[i][j] + bj[j];
                *(float4*)(out + (long long)n * 256 + cg * 8)     = make_float4(vv[0], vv[1], vv[2], vv[3]);
                *(float4*)(out + (long long)n * 256 + cg * 8 + 4) = make_float4(vv[4], vv[5], vv[6], vv[7]);
            }
        }
    }
}

// ======================================================================
// launch
// ======================================================================
extern "C" void kernel_launch(void* const* d_in, const int* in_sizes, int n_in,
                              void* d_out, int out_size)
{
    const float* x  = (const float*)d_in[0];
    const void*  ei = d_in[1];
    const float* ea = (const float*)d_in[2];
    const float* w1a = (const float*)d_in[5];
    const float* b1a = (const float*)d_in[6];
    const float* w1b = (const float*)d_in[7];
    const float* b1b = (const float*)d_in[8];
    const float* w2a = (const float*)d_in[9];
    const float* b2a = (const float*)d_in[10];
    const float* w2b = (const float*)d_in[11];
    const float* b2b = (const float*)d_in[12];
    float* out = (float*)d_out;

    const int N = in_sizes[0] / 128;
    const int E = in_sizes[1] / 2;

    unsigned char *w1blob = nullptr, *w2blob = nullptr;
    cudaGetSymbolAddress((void**)&w1blob, g_w1blob);
    cudaGetSymbolAddress((void**)&w2blob, g_w2blob);

    const int NODE_SMEM = (64 * 384 + 16 * 256) * 4;
    cudaFuncSetAttribute(edge_mma_kernel, cudaFuncAttributeMaxDynamicSharedMemorySize, EDGE_SMEM);
    cudaFuncSetAttribute(node_mlp_kernel, cudaFuncAttributeMaxDynamicSharedMemorySize, NODE_SMEM);

    detect_idx_kernel<<<1, 256>>>((const int*)ei);
    zero_kernel<<<1024, 256>>>(N);
    prep_weights_kernel<<<128, 512>>>(w1a, w1blob);
    prep_weights_kernel<<<128, 512>>>(w1b, w2blob);
    edge_mma_kernel<<<(E + 127) / 128, 512, EDGE_SMEM>>>(x, ei, ea, b1a, b1b, E, N);
    node_mlp_kernel<<<(N + 63) / 64, 256, NODE_SMEM>>>(x, w2a, b2a, w2b, b2b, out, N);
}

// round 11
// speedup vs baseline: 1.1210x; 1.1210x over previous
#include <cuda_runtime.h>
#include <cuda_bf16.h>
#include <cstdint>

// ---------------- problem constants ----------------
#define MAXN 50000

// ---------------- device scratch ----------------
__device__ float g_sums[MAXN * 256];
__device__ int   g_cnt [MAXN];
__device__ int   g_idx64;
// weight blobs: per layer 16 k16-chunks x [hi 12288 | lo 12288] = 393216 B
// inside a subchunk: [n (256)][stride 48 B], element (n, kk) at n*48 + kk*2
#define SUB_BYTES 12288
__device__ __align__(16) unsigned char g_w1blob[32 * SUB_BYTES];
__device__ __align__(16) unsigned char g_w2blob[32 * SUB_BYTES];

// ---------------- smem layout (bytes) ----------------
#define A_STRIDE_B 528              // 264 halves per row (256 + 8 pad)
#define SA_HI  0                    // 64 * 528 = 33792
#define SA_LO  33792
#define SB0    67584                // 12288
#define SB1    79872                // 12288
#define SBIA   92160                // b1a, 256 floats
#define SBIB   93184                // b1b, 256 floats
#define SROW   94208                // 64 ints
#define SCOL   94464
#define EDGE_SMEM 94720

// ---------------- helpers ----------------
__device__ __forceinline__ uint32_t smem_u32(const void* p) {
    uint32_t a;
    asm("{ .reg .u64 t; cvta.to.shared.u64 t, %1; cvt.u32.u64 %0, t; }" : "=r"(a) : "l"(p));
    return a;
}
__device__ __forceinline__ void cp16(uint32_t saddr, const void* gaddr) {
    asm volatile("cp.async.cg.shared.global [%0], [%1], 16;" :: "r"(saddr), "l"(gaddr));
}
#define CP_COMMIT() asm volatile("cp.async.commit_group;")
#define CP_WAIT1()  asm volatile("cp.async.wait_group 1;")

__device__ __forceinline__ void red_add_v2(float* p, float a, float b) {
    asm volatile("red.global.add.v2.f32 [%0], {%1, %2};" :: "l"(p), "f"(a), "f"(b) : "memory");
}
__device__ __forceinline__ void mma16816(float* c, const uint32_t* a, const uint32_t* b) {
    asm volatile(
        "mma.sync.aligned.m16n8k16.row.col.f32.bf16.bf16.f32 "
        "{%0,%1,%2,%3}, {%4,%5,%6,%7}, {%8,%9}, {%0,%1,%2,%3};"
        : "+f"(c[0]), "+f"(c[1]), "+f"(c[2]), "+f"(c[3])
        : "r"(a[0]), "r"(a[1]), "r"(a[2]), "r"(a[3]), "r"(b[0]), "r"(b[1]));
}
__device__ __forceinline__ void ldm_x4(uint32_t addr, uint32_t* r) {
    asm volatile("ldmatrix.sync.aligned.m8n8.x4.shared.b16 {%0,%1,%2,%3}, [%4];"
                 : "=r"(r[0]), "=r"(r[1]), "=r"(r[2]), "=r"(r[3]) : "r"(addr));
}
__device__ __forceinline__ void split2(float v0, float v1, uint32_t& hi, uint32_t& lo) {
    __nv_bfloat16 h0 = __float2bfloat16(v0), h1 = __float2bfloat16(v1);
    __nv_bfloat162 hh{h0, h1};
    __nv_bfloat162 ll{__float2bfloat16(v0 - __bfloat162float(h0)),
                      __float2bfloat16(v1 - __bfloat162float(h1))};
    hi = *(uint32_t*)&hh;
    lo = *(uint32_t*)&ll;
}

// ======================================================================
// detect index dtype
// ======================================================================
__global__ void detect_idx_kernel(const int* __restrict__ ei_raw) {
    __shared__ int any_nonzero;
    if (threadIdx.x == 0) any_nonzero = 0;
    __syncthreads();
    for (int i = threadIdx.x; i < 1024; i += blockDim.x)
        if (ei_raw[2 * i + 1] != 0) any_nonzero = 1;
    __syncthreads();
    if (threadIdx.x == 0) g_idx64 = (any_nonzero == 0) ? 1 : 0;
}
__device__ __forceinline__ int load_idx(const void* ei, long long pos, int nmax) {
    int v = g_idx64 ? (int)((const long long*)ei)[pos] : ((const int*)ei)[pos];
    return min(max(v, 0), nmax - 1);
}

// ======================================================================
// zero scratch
// ======================================================================
__global__ void zero_kernel(int n_nodes) {
    int tid = blockIdx.x * blockDim.x + threadIdx.x;
    int stride = gridDim.x * blockDim.x;
    int tot4 = n_nodes * 64;
    float4* s4 = (float4*)g_sums;
    float4 z = make_float4(0.f, 0.f, 0.f, 0.f);
    for (int i = tid; i < tot4; i += stride) s4[i] = z;
    for (int i = tid; i < n_nodes; i += stride) g_cnt[i] = 0;
}

// ======================================================================
// prep: w [256 K][256 N] fp32 -> subchunks (B^T, 48B padded rows)
//   sub 2*(k>>4)   : hi, element at n*48 + (k&15)*2
//   sub 2*(k>>4)+1 : lo
// ======================================================================
__global__ void prep_weights_kernel(const float* __restrict__ w, unsigned char* __restrict__ blob) {
    int idx = blockIdx.x * blockDim.x + threadIdx.x;
    if (idx >= 256 * 256) return;
    int k = idx >> 8, n = idx & 255;
    float v = w[idx];
    __nv_bfloat16 hi = __float2bfloat16(v);
    __nv_bfloat16 lo = __float2bfloat16(v - __bfloat162float(hi));
    unsigned char* base = blob + (uint32_t)(k >> 4) * (2 * SUB_BYTES) + n * 48 + (k & 15) * 2;
    *(__nv_bfloat16*)(base)             = hi;
    *(__nv_bfloat16*)(base + SUB_BYTES) = lo;
}

// ======================================================================
// edge kernel: HMMA bf16-3split, 64 edges / CTA, 256 threads, 2 CTA/SM
// ======================================================================
__global__ __launch_bounds__(256, 2)
void edge_mma_kernel(const float* __restrict__ x,
                     const void* __restrict__ edge_index,
                     const float* __restrict__ edge_attr,
                     const float* __restrict__ b1a, const float* __restrict__ b1b,
                     int E, int N)
{
    extern __shared__ __align__(16) unsigned char smem[];
    const uint32_t sbase = smem_u32(smem);
    const int tid  = threadIdx.x;
    const int lane = tid & 31;
    const int w    = tid >> 5;          // 8 warps
    const int g    = lane >> 2;         // 0..7
    const int tg   = lane & 3;          // 0..3
    const int mb   = (w >> 2) * 32;     // warp M base (0/32)
    const int nb   = (w & 3) * 64;      // warp N base (0/64/128/192)
    const int sel  = lane >> 3;         // 0..3 (ldmatrix matrix select)
    const int rin  = lane & 7;          // row within 8x8 matrix

    const int e0 = blockIdx.x * 64;
    const int ecnt = min(64, E - e0);
    int*   srow = (int*)(smem + SROW);
    int*   scol = (int*)(smem + SCOL);
    float* sba  = (float*)(smem + SBIA);
    float* sbb  = (float*)(smem + SBIB);

    if (tid < 64) {
        int r = -1, c = -1;
        if (tid < ecnt) {
            r = load_idx(edge_index, (long long)(e0 + tid), N);
            c = load_idx(edge_index, (long long)E + e0 + tid, N);
            atomicAdd(&g_cnt[c], 1);
        }
        srow[tid] = r;
        scol[tid] = c;
    }
    if (tid < 256) {
        sba[tid] = b1a[tid];
        sbb[tid] = b1b[tid];
    }
    __syncthreads();

    // ---- gather inputs, split, store to A_hi/A_lo (padded rows) ----
    for (int idx = tid; idx < 64 * 32; idx += 256) {        // x : k = c4*4
        int e = idx >> 5, c4 = idx & 31;
        float4 v = make_float4(0.f, 0.f, 0.f, 0.f);
        if (e < ecnt) v = *(const float4*)(x + (long long)srow[e] * 128 + c4 * 4);
        uint32_t h0, l0, h1, l1;
        split2(v.x, v.y, h0, l0);
        split2(v.z, v.w, h1, l1);
        uint32_t off = (uint32_t)e * A_STRIDE_B + (uint32_t)c4 * 8;
        *(uint2*)(smem + SA_HI + off) = make_uint2(h0, h1);
        *(uint2*)(smem + SA_LO + off) = make_uint2(l0, l1);
    }
    for (int idx = tid; idx < 64 * 32; idx += 256) {        // edge_attr : k = 128 + c4*4
        int e = idx >> 5, c4 = idx & 31;
        float4 v = make_float4(0.f, 0.f, 0.f, 0.f);
        if (e < ecnt) v = *(const float4*)(edge_attr + (long long)(e0 + e) * 128 + c4 * 4);
        uint32_t h0, l0, h1, l1;
        split2(v.x, v.y, h0, l0);
        split2(v.z, v.w, h1, l1);
        uint32_t off = (uint32_t)e * A_STRIDE_B + 256u + (uint32_t)c4 * 8;
        *(uint2*)(smem + SA_HI + off) = make_uint2(h0, h1);
        *(uint2*)(smem + SA_LO + off) = make_uint2(l0, l1);
    }
    __syncthreads();

    float acc[2][8][4];
    #pragma unroll
    for (int mt = 0; mt < 2; mt++)
        #pragma unroll
        for (int nt = 0; nt < 8; nt++)
            #pragma unroll
            for (int i = 0; i < 4; i++) acc[mt][nt][i] = 0.f;

    // subchunk copy: 768 x 16B with 256 threads (3 each)
    #define CP_SUB(GSRC, SDST)                                             \
        {                                                                  \
            const unsigned char* _g = (GSRC);                              \
            uint32_t _s = sbase + (SDST);                                  \
            _Pragma("unroll")                                              \
            for (int _j = 0; _j < 3; _j++)                                 \
                cp16(_s + (tid + _j * 256) * 16, _g + (tid + _j * 256) * 16); \
        }

    // A fragment load for k16 index c (both splits)
    #define A_LOAD(C)                                                      \
        _Pragma("unroll")                                                  \
        for (int mt = 0; mt < 2; mt++) {                                   \
            uint32_t row = (uint32_t)(mb + mt * 16 + ((sel & 1) << 3) + rin); \
            uint32_t byt = row * A_STRIDE_B + (uint32_t)(C) * 32 + ((sel >> 1) << 4); \
            ldm_x4(sbase + SA_HI + byt, ahi[mt]);                          \
            ldm_x4(sbase + SA_LO + byt, alo[mt]);                          \
        }

    // B subchunk pass; NTERMS=2 -> (ahi+alo)*b ; NTERMS=1 -> ahi*b
    #define B_PASS(SBCUR, NTERMS)                                          \
        _Pragma("unroll")                                                  \
        for (int j = 0; j < 8; j += 2) {                                   \
            uint32_t n = (uint32_t)(nb + (j + (sel >> 1)) * 8 + rin);      \
            uint32_t byt = n * 48u + ((uint32_t)(sel & 1) << 4);           \
            uint32_t b[4];                                                 \
            ldm_x4(sbase + (SBCUR) + byt, b);                              \
            _Pragma("unroll")                                              \
            for (int mt = 0; mt < 2; mt++) {                               \
                mma16816(acc[mt][j],     ahi[mt], b);                      \
                mma16816(acc[mt][j + 1], ahi[mt], b + 2);                  \
                if (NTERMS == 2) {                                         \
                    mma16816(acc[mt][j],     alo[mt], b);                  \
                    mma16816(acc[mt][j + 1], alo[mt], b + 2);              \
                }                                                          \
            }                                                              \
        }

    uint32_t ahi[2][4], alo[2][4];

    // ---- GEMM1: [x|ea] (64x256) @ w1a -> acc  (32 subchunks) ----
    CP_SUB(g_w1blob, SB0);
    CP_COMMIT();
    for (int s = 0; s < 32; s++) {
        if (s < 31) { CP_SUB(g_w1blob + (s + 1) * SUB_BYTES, ((s + 1) & 1) ? SB1 : SB0); }
        else        { CP_SUB(g_w2blob, SB0); }   // prefetch GEMM2 sub 0
        CP_COMMIT();
        CP_WAIT1();
        __syncthreads();
        uint32_t sb = (s & 1) ? SB1 : SB0;
        if (!(s & 1)) {                 // hi subchunk: load A frags, 2 terms
            A_LOAD(s >> 1);
            B_PASS(sb, 2);
        } else {                        // lo subchunk: reuse ahi, 1 term
            B_PASS(sb, 1);
        }
        __syncthreads();
    }

    // ---- layer-1 epilogue: bias + ELU + re-split -> overwrite A ----
    {
        #pragma unroll
        for (int mt = 0; mt < 2; mt++) {
            uint32_t r0 = (uint32_t)(mb + mt * 16 + g);
            #pragma unroll
            for (int nt = 0; nt < 8; nt++) {
                int cb = nb + nt * 8 + tg * 2;
                float b0 = sba[cb], b1 = sba[cb + 1];
                float v00 = acc[mt][nt][0] + b0, v01 = acc[mt][nt][1] + b1;
                float v10 = acc[mt][nt][2] + b0, v11 = acc[mt][nt][3] + b1;
                v00 = (v00 > 0.f) ? v00 : expm1f(v00);
                v01 = (v01 > 0.f) ? v01 : expm1f(v01);
                v10 = (v10 > 0.f) ? v10 : expm1f(v10);
                v11 = (v11 > 0.f) ? v11 : expm1f(v11);
                uint32_t hi, lo;
                uint32_t o = r0 * A_STRIDE_B + (uint32_t)cb * 2;
                split2(v00, v01, hi, lo);
                *(uint32_t*)(smem + SA_HI + o) = hi;
                *(uint32_t*)(smem + SA_LO + o) = lo;
                o += 8 * A_STRIDE_B;
                split2(v10, v11, hi, lo);
                *(uint32_t*)(smem + SA_HI + o) = hi;
                *(uint32_t*)(smem + SA_LO + o) = lo;
                acc[mt][nt][0] = 0.f; acc[mt][nt][1] = 0.f;
                acc[mt][nt][2] = 0.f; acc[mt][nt][3] = 0.f;
            }
        }
    }
    __syncthreads();

    // ---- GEMM2: elu(H1) (64x256) @ w1b -> acc ----
    for (int s = 0; s < 32; s++) {
        if (s < 31) { CP_SUB(g_w2blob + (s + 1) * SUB_BYTES, ((s + 1) & 1) ? SB1 : SB0); }
        CP_COMMIT();
        CP_WAIT1();
        __syncthreads();
        uint32_t sb = (s & 1) ? SB1 : SB0;
        if (!(s & 1)) {
            A_LOAD(s >> 1);
            B_PASS(sb, 2);
        } else {
            B_PASS(sb, 1);
        }
        __syncthreads();
    }

    // ---- scatter epilogue: + b1b, red.global.add.v2 into g_sums ----
    {
        #pragma unroll
        for (int mt = 0; mt < 2; mt++) {
            int er0 = mb + mt * 16 + g;
            int c0 = scol[er0];
            int c1 = scol[er0 + 8];
            float* p0 = (c0 >= 0) ? (g_sums + (long long)c0 * 256) : nullptr;
            float* p1 = (c1 >= 0) ? (g_sums + (long long)c1 * 256) : nullptr;
            #pragma unroll
            for (int nt = 0; nt < 8; nt++) {
                int cb = nb + nt * 8 + tg * 2;
                float b0 = sbb[cb], b1 = sbb[cb + 1];
                if (p0) red_add_v2(p0 + cb, acc[mt][nt][0] + b0, acc[mt][nt][1] + b1);
                if (p1) red_add_v2(p1 + cb, acc[mt][nt][2] + b0, acc[mt][nt][3] + b1);
            }
        }
    }
}

// ======================================================================
// node MLP (scalar fp32)
// ======================================================================
__global__ __launch_bounds__(256)
void node_mlp_kernel(const float* __restrict__ x,
                     const float* __restrict__ w2a, const float* __restrict__ b2a,
                     const float* __restrict__ w2b, const float* __restrict__ b2b,
                     float* __restrict__ out, int N)
{
    extern __shared__ float smemf[];
    float* buf  = smemf;             // 64*384
    float* wbuf = smemf + 64 * 384;  // 16*256
    __shared__ float sInv[64];

    const int tid = threadIdx.x;
    const int er  = tid >> 5;
    const int cg  = tid & 31;
    const int n0  = blockIdx.x * 64;
    const int ncnt = min(64, N - n0);

    if (tid < 64) {
        float inv = 0.f;
        if (tid < ncnt) inv = 1.0f / (float)max(g_cnt[n0 + tid], 1);
        sInv[tid] = inv;
    }
    __syncthreads();

    for (int idx = tid; idx < 64 * 32; idx += 256) {
        int e = idx >> 5, c4 = idx & 31;
        float4 v = make_float4(0.f, 0.f, 0.f, 0.f);
        if (e < ncnt) v = *(const float4*)(x + (long long)(n0 + e) * 128 + c4 * 4);
        *(float4*)(buf + e * 384 + c4 * 4) = v;
    }
    for (int idx = tid; idx < 64 * 64; idx += 256) {
        int e = idx >> 6, c4 = idx & 63;
        float4 v = make_float4(0.f, 0.f, 0.f, 0.f);
        if (e < ncnt) {
            v = *(const float4*)(g_sums + (long long)(n0 + e) * 256 + c4 * 4);
            float inv = sInv[e];
            v.x *= inv; v.y *= inv; v.z *= inv; v.w *= inv;
        }
        *(float4*)(buf + e * 384 + 128 + c4 * 4) = v;
    }

    float acc[8][8];
    #pragma unroll
    for (int i = 0; i < 8; i++)
        #pragma unroll
        for (int j = 0; j < 8; j++) acc[i][j] = 0.f;

    for (int k0 = 0; k0 < 384; k0 += 16) {
        __syncthreads();
        const float4* wsrc = (const float4*)(w2a + k0 * 256);
        float4* wd = (float4*)wbuf;
        #pragma unroll
        for (int t = 0; t < 4; t++) wd[tid + t * 256] = wsrc[tid + t * 256];
        __syncthreads();
        #pragma unroll
        for (int kk = 0; kk < 16; kk++) {
            float a[8];
            #pragma unroll
            for (int i = 0; i < 8; i++) a[i] = buf[(er * 8 + i) * 384 + k0 + kk];
            float4 b0 = *(float4*)(wbuf + kk * 256 + cg * 8);
            float4 b1 = *(float4*)(wbuf + kk * 256 + cg * 8 + 4);
            float b[8] = {b0.x, b0.y, b0.z, b0.w, b1.x, b1.y, b1.z, b1.w};
            #pragma unroll
            for (int i = 0; i < 8; i++)
                #pragma unroll
                for (int j = 0; j < 8; j++) acc[i][j] = fmaf(a[i], b[j], acc[i][j]);
        }
    }

    __syncthreads();
    {
        float bj[8];
        #pragma unroll
        for (int j = 0; j < 8; j++) bj[j] = b2a[cg * 8 + j];
        #pragma unroll
        for (int i = 0; i < 8; i++) {
            float vv[8];
            #pragma unroll
            for (int j = 0; j < 8; j++) {
                float v = acc[i][j] + bj[j];
                vv[j] = (v > 0.f) ? v : expm1f(v);
                acc[i][j] = 0.f;
            }
            *(float4*)(buf + (er * 8 + i) * 256 + cg * 8)     = make_float4(vv[0], vv[1], vv[2], vv[3]);
            *(float4*)(buf + (er * 8 + i) * 256 + cg * 8 + 4) = make_float4(vv[4], vv[5], vv[6], vv[7]);
        }
    }

    for (int k0 = 0; k0 < 256; k0 += 16) {
        __syncthreads();
        const float4* wsrc = (const float4*)(w2b + k0 * 256);
        float4* wd = (float4*)wbuf;
        #pragma unroll
        for (int t = 0; t < 4; t++) wd[tid + t * 256] = wsrc[tid + t * 256];
        __syncthreads();
        #pragma unroll
        for (int kk = 0; kk < 16; kk++) {
            float a[8];
            #pragma unroll
            for (int i = 0; i < 8; i++) a[i] = buf[(er * 8 + i) * 256 + k0 + kk];
            float4 b0 = *(float4*)(wbuf + kk * 256 + cg * 8);
            float4 b1 = *(float4*)(wbuf + kk * 256 + cg * 8 + 4);
            float b[8] = {b0.x, b0.y, b0.z, b0.w, b1.x, b1.y, b1.z, b1.w};
            #pragma unroll
            for (int i = 0; i < 8; i++)
                #pragma unroll
                for (int j = 0; j < 8; j++) acc[i][j] = fmaf(a[i], b[j], acc[i][j]);
        }
    }

    {
        float bj[8];
        #pragma unroll
        for (int j = 0; j < 8; j++) bj[j] = b2b[cg * 8 + j];
        #pragma unroll
        for (int i = 0; i < 8; i++) {
            int n = n0 + er * 8 + i;
            if (n < N) {
                float vv[8];
                #pragma unroll
                for (int j = 0; j < 8; j++) vv[j] = acc[i][j] + bj[j];
                *(float4*)(out + (long long)n * 256 + cg * 8)     = make_float4(vv[0], vv[1], vv[2], vv[3]);
                *(float4*)(out + (long long)n * 256 + cg * 8 + 4) = make_float4(vv[4], vv[5], vv[6], vv[7]);
            }
        }
    }
}

// ======================================================================
// launch
// ======================================================================
extern "C" void kernel_launch(void* const* d_in, const int* in_sizes, int n_in,
                              void* d_out, int out_size)
{
    const float* x  = (const float*)d_in[0];
    const void*  ei = d_in[1];
    const float* ea = (const float*)d_in[2];
    const float* w1a = (const float*)d_in[5];
    const float* b1a = (const float*)d_in[6];
    const float* w1b = (const float*)d_in[7];
    const float* b1b = (const float*)d_in[8];
    const float* w2a = (const float*)d_in[9];
    const float* b2a = (const float*)d_in[10];
    const float* w2b = (const float*)d_in[11];
    const float* b2b = (const float*)d_in[12];
    float* out = (float*)d_out;

    const int N = in_sizes[0] / 128;
    const int E = in_sizes[1] / 2;

    unsigned char *w1blob = nullptr, *w2blob = nullptr;
    cudaGetSymbolAddress((void**)&w1blob, g_w1blob);
    cudaGetSymbolAddress((void**)&w2blob, g_w2blob);

    const int NODE_SMEM = (64 * 384 + 16 * 256) * 4;
    cudaFuncSetAttribute(edge_mma_kernel, cudaFuncAttributeMaxDynamicSharedMemorySize, EDGE_SMEM);
    cudaFuncSetAttribute(node_mlp_kernel, cudaFuncAttributeMaxDynamicSharedMemorySize, NODE_SMEM);

    detect_idx_kernel<<<1, 256>>>((const int*)ei);
    zero_kernel<<<1024, 256>>>(N);
    prep_weights_kernel<<<128, 512>>>(w1a, w1blob);
    prep_weights_kernel<<<128, 512>>>(w1b, w2blob);
    edge_mma_kernel<<<(E + 63) / 64, 256, EDGE_SMEM>>>(x, ei, ea, b1a, b1b, E, N);
    node_mlp_kernel<<<(N + 63) / 64, 256, NODE_SMEM>>>(x, w2a, b2a, w2b, b2b, out, N);
}

// round 12
// speedup vs baseline: 1.1929x; 1.0642x over previous
#include <cuda_runtime.h>
#include <cuda_bf16.h>
#include <cstdint>

// ---------------- problem constants ----------------
#define MAXN 50000

// ---------------- device scratch ----------------
__device__ float g_sums[MAXN * 256];
__device__ int   g_cnt [MAXN];
__device__ int   g_idx64;
// weight blobs: subchunk = one k16 slice, [n (256)][stride 48 B], hi then lo
#define SUB_BYTES 12288
__device__ __align__(16) unsigned char g_w1blob[32 * SUB_BYTES];   // w1a (K=256)
__device__ __align__(16) unsigned char g_w2blob[32 * SUB_BYTES];   // w1b (K=256)
__device__ __align__(16) unsigned char g_wnablob[48 * SUB_BYTES];  // w2a (K=384)
__device__ __align__(16) unsigned char g_wnbblob[32 * SUB_BYTES];  // w2b (K=256)

// ---------------- edge smem layout (bytes) ----------------
#define A_STRIDE_B 528              // 264 halves per row (256 + 8 pad)
#define SA_HI  0
#define SA_LO  33792
#define SB0    67584
#define SB1    79872
#define SBIA   92160
#define SBIB   93184
#define SROW   94208
#define SCOL   94464
#define EDGE_SMEM 94720

// ---------------- node smem layout (bytes) ----------------
#define NA_STRIDE_B 784             // 392 halves per row (384 + 8 pad)
#define NA_HI  0                    // 64*784 = 50176
#define NA_LO  50176
#define NB0    100352
#define NB1    112640
#define NB2A   124928               // b2a 256 floats
#define NB2B   125952               // b2b 256 floats
#define NSINV  126976               // 64 floats
#define NODE_SMEM 127232

// ---------------- helpers ----------------
__device__ __forceinline__ uint32_t smem_u32(const void* p) {
    uint32_t a;
    asm("{ .reg .u64 t; cvta.to.shared.u64 t, %1; cvt.u32.u64 %0, t; }" : "=r"(a) : "l"(p));
    return a;
}
__device__ __forceinline__ void cp16(uint32_t saddr, const void* gaddr) {
    asm volatile("cp.async.cg.shared.global [%0], [%1], 16;" :: "r"(saddr), "l"(gaddr));
}
#define CP_COMMIT() asm volatile("cp.async.commit_group;")
#define CP_WAIT1()  asm volatile("cp.async.wait_group 1;")

__device__ __forceinline__ void red_add_v2(float* p, float a, float b) {
    asm volatile("red.global.add.v2.f32 [%0], {%1, %2};" :: "l"(p), "f"(a), "f"(b) : "memory");
}
__device__ __forceinline__ void mma16816(float* c, const uint32_t* a, const uint32_t* b) {
    asm volatile(
        "mma.sync.aligned.m16n8k16.row.col.f32.bf16.bf16.f32 "
        "{%0,%1,%2,%3}, {%4,%5,%6,%7}, {%8,%9}, {%0,%1,%2,%3};"
        : "+f"(c[0]), "+f"(c[1]), "+f"(c[2]), "+f"(c[3])
        : "r"(a[0]), "r"(a[1]), "r"(a[2]), "r"(a[3]), "r"(b[0]), "r"(b[1]));
}
__device__ __forceinline__ void ldm_x4(uint32_t addr, uint32_t* r) {
    asm volatile("ldmatrix.sync.aligned.m8n8.x4.shared.b16 {%0,%1,%2,%3}, [%4];"
                 : "=r"(r[0]), "=r"(r[1]), "=r"(r[2]), "=r"(r[3]) : "r"(addr));
}
__device__ __forceinline__ void split2(float v0, float v1, uint32_t& hi, uint32_t& lo) {
    __nv_bfloat16 h0 = __float2bfloat16(v0), h1 = __float2bfloat16(v1);
    __nv_bfloat162 hh{h0, h1};
    __nv_bfloat162 ll{__float2bfloat16(v0 - __bfloat162float(h0)),
                      __float2bfloat16(v1 - __bfloat162float(h1))};
    hi = *(uint32_t*)&hh;
    lo = *(uint32_t*)&ll;
}

// ======================================================================
// detect index dtype
// ======================================================================
__global__ void detect_idx_kernel(const int* __restrict__ ei_raw) {
    __shared__ int any_nonzero;
    if (threadIdx.x == 0) any_nonzero = 0;
    __syncthreads();
    for (int i = threadIdx.x; i < 1024; i += blockDim.x)
        if (ei_raw[2 * i + 1] != 0) any_nonzero = 1;
    __syncthreads();
    if (threadIdx.x == 0) g_idx64 = (any_nonzero == 0) ? 1 : 0;
}
__device__ __forceinline__ int load_idx(const void* ei, long long pos, int nmax) {
    int v = g_idx64 ? (int)((const long long*)ei)[pos] : ((const int*)ei)[pos];
    return min(max(v, 0), nmax - 1);
}

// ======================================================================
// zero scratch
// ======================================================================
__global__ void zero_kernel(int n_nodes) {
    int tid = blockIdx.x * blockDim.x + threadIdx.x;
    int stride = gridDim.x * blockDim.x;
    int tot4 = n_nodes * 64;
    float4* s4 = (float4*)g_sums;
    float4 z = make_float4(0.f, 0.f, 0.f, 0.f);
    for (int i = tid; i < tot4; i += stride) s4[i] = z;
    for (int i = tid; i < n_nodes; i += stride) g_cnt[i] = 0;
}

// ======================================================================
// prep: w [K][256 N] fp32 -> subchunks (B^T, 48B padded rows)
//   sub 2*(k>>4) : hi at n*48 + (k&15)*2 ; sub 2*(k>>4)+1 : lo
// ======================================================================
__global__ void prep_weights_kernel(const float* __restrict__ w, unsigned char* __restrict__ blob, int K) {
    int idx = blockIdx.x * blockDim.x + threadIdx.x;
    if (idx >= K * 256) return;
    int k = idx >> 8, n = idx & 255;
    float v = w[idx];
    __nv_bfloat16 hi = __float2bfloat16(v);
    __nv_bfloat16 lo = __float2bfloat16(v - __bfloat162float(hi));
    unsigned char* base = blob + (uint32_t)(k >> 4) * (2 * SUB_BYTES) + n * 48 + (k & 15) * 2;
    *(__nv_bfloat16*)(base)             = hi;
    *(__nv_bfloat16*)(base + SUB_BYTES) = lo;
}

// ---- shared GEMM machinery macros ----
#define CP_SUB(GSRC, SDST)                                             \
    {                                                                  \
        const unsigned char* _g = (GSRC);                              \
        uint32_t _s = sbase + (SDST);                                  \
        _Pragma("unroll")                                              \
        for (int _j = 0; _j < 3; _j++)                                 \
            cp16(_s + (tid + _j * 256) * 16, _g + (tid + _j * 256) * 16); \
    }

#define A_LOAD(SAHI, SALO, STRIDE, C)                                  \
    _Pragma("unroll")                                                  \
    for (int mt = 0; mt < 2; mt++) {                                   \
        uint32_t row = (uint32_t)(mb + mt * 16 + ((sel & 1) << 3) + rin); \
        uint32_t byt = row * (STRIDE) + (uint32_t)(C) * 32 + ((sel >> 1) << 4); \
        ldm_x4(sbase + (SAHI) + byt, ahi[mt]);                         \
        ldm_x4(sbase + (SALO) + byt, alo[mt]);                         \
    }

#define B_PASS(SBCUR, NTERMS)                                          \
    _Pragma("unroll")                                                  \
    for (int j = 0; j < 8; j += 2) {                                   \
        uint32_t n = (uint32_t)(nb + (j + (sel >> 1)) * 8 + rin);      \
        uint32_t byt = n * 48u + ((uint32_t)(sel & 1) << 4);           \
        uint32_t b[4];                                                 \
        ldm_x4(sbase + (SBCUR) + byt, b);                              \
        _Pragma("unroll")                                              \
        for (int mt = 0; mt < 2; mt++) {                               \
            mma16816(acc[mt][j],     ahi[mt], b);                      \
            mma16816(acc[mt][j + 1], ahi[mt], b + 2);                  \
            if (NTERMS == 2) {                                         \
                mma16816(acc[mt][j],     alo[mt], b);                  \
                mma16816(acc[mt][j + 1], alo[mt], b + 2);              \
            }                                                          \
        }                                                              \
    }

// ======================================================================
// edge kernel: HMMA bf16-3split, 64 edges / CTA, 256 threads, 2 CTA/SM
// ======================================================================
__global__ __launch_bounds__(256, 2)
void edge_mma_kernel(const float* __restrict__ x,
                     const void* __restrict__ edge_index,
                     const float* __restrict__ edge_attr,
                     const float* __restrict__ b1a, const float* __restrict__ b1b,
                     int E, int N)
{
    extern __shared__ __align__(16) unsigned char smem[];
    const uint32_t sbase = smem_u32(smem);
    const int tid  = threadIdx.x;
    const int lane = tid & 31;
    const int w    = tid >> 5;
    const int g    = lane >> 2;
    const int tg   = lane & 3;
    const int mb   = (w >> 2) * 32;
    const int nb   = (w & 3) * 64;
    const int sel  = lane >> 3;
    const int rin  = lane & 7;

    const int e0 = blockIdx.x * 64;
    const int ecnt = min(64, E - e0);
    int*   srow = (int*)(smem + SROW);
    int*   scol = (int*)(smem + SCOL);
    float* sba  = (float*)(smem + SBIA);
    float* sbb  = (float*)(smem + SBIB);

    if (tid < 64) {
        int r = -1, c = -1;
        if (tid < ecnt) {
            r = load_idx(edge_index, (long long)(e0 + tid), N);
            c = load_idx(edge_index, (long long)E + e0 + tid, N);
            atomicAdd(&g_cnt[c], 1);
        }
        srow[tid] = r;
        scol[tid] = c;
    }
    if (tid < 256) {
        sba[tid] = b1a[tid];
        sbb[tid] = b1b[tid];
    }
    __syncthreads();

    for (int idx = tid; idx < 64 * 32; idx += 256) {
        int e = idx >> 5, c4 = idx & 31;
        float4 v = make_float4(0.f, 0.f, 0.f, 0.f);
        if (e < ecnt) v = *(const float4*)(x + (long long)srow[e] * 128 + c4 * 4);
        uint32_t h0, l0, h1, l1;
        split2(v.x, v.y, h0, l0);
        split2(v.z, v.w, h1, l1);
        uint32_t off = (uint32_t)e * A_STRIDE_B + (uint32_t)c4 * 8;
        *(uint2*)(smem + SA_HI + off) = make_uint2(h0, h1);
        *(uint2*)(smem + SA_LO + off) = make_uint2(l0, l1);
    }
    for (int idx = tid; idx < 64 * 32; idx += 256) {
        int e = idx >> 5, c4 = idx & 31;
        float4 v = make_float4(0.f, 0.f, 0.f, 0.f);
        if (e < ecnt) v = *(const float4*)(edge_attr + (long long)(e0 + e) * 128 + c4 * 4);
        uint32_t h0, l0, h1, l1;
        split2(v.x, v.y, h0, l0);
        split2(v.z, v.w, h1, l1);
        uint32_t off = (uint32_t)e * A_STRIDE_B + 256u + (uint32_t)c4 * 8;
        *(uint2*)(smem + SA_HI + off) = make_uint2(h0, h1);
        *(uint2*)(smem + SA_LO + off) = make_uint2(l0, l1);
    }
    __syncthreads();

    float acc[2][8][4];
    #pragma unroll
    for (int mt = 0; mt < 2; mt++)
        #pragma unroll
        for (int nt = 0; nt < 8; nt++)
            #pragma unroll
            for (int i = 0; i < 4; i++) acc[mt][nt][i] = 0.f;

    uint32_t ahi[2][4], alo[2][4];

    // ---- GEMM1 ----
    CP_SUB(g_w1blob, SB0);
    CP_COMMIT();
    for (int s = 0; s < 32; s++) {
        if (s < 31) { CP_SUB(g_w1blob + (s + 1) * SUB_BYTES, ((s + 1) & 1) ? SB1 : SB0); }
        else        { CP_SUB(g_w2blob, SB0); }
        CP_COMMIT();
        CP_WAIT1();
        __syncthreads();
        uint32_t sb = (s & 1) ? SB1 : SB0;
        if (!(s & 1)) { A_LOAD(SA_HI, SA_LO, A_STRIDE_B, s >> 1); B_PASS(sb, 2); }
        else          { B_PASS(sb, 1); }
        __syncthreads();
    }

    // ---- layer-1 epilogue ----
    {
        #pragma unroll
        for (int mt = 0; mt < 2; mt++) {
            uint32_t r0 = (uint32_t)(mb + mt * 16 + g);
            #pragma unroll
            for (int nt = 0; nt < 8; nt++) {
                int cb = nb + nt * 8 + tg * 2;
                float b0 = sba[cb], b1 = sba[cb + 1];
                float v00 = acc[mt][nt][0] + b0, v01 = acc[mt][nt][1] + b1;
                float v10 = acc[mt][nt][2] + b0, v11 = acc[mt][nt][3] + b1;
                v00 = (v00 > 0.f) ? v00 : expm1f(v00);
                v01 = (v01 > 0.f) ? v01 : expm1f(v01);
                v10 = (v10 > 0.f) ? v10 : expm1f(v10);
                v11 = (v11 > 0.f) ? v11 : expm1f(v11);
                uint32_t hi, lo;
                uint32_t o = r0 * A_STRIDE_B + (uint32_t)cb * 2;
                split2(v00, v01, hi, lo);
                *(uint32_t*)(smem + SA_HI + o) = hi;
                *(uint32_t*)(smem + SA_LO + o) = lo;
                o += 8 * A_STRIDE_B;
                split2(v10, v11, hi, lo);
                *(uint32_t*)(smem + SA_HI + o) = hi;
                *(uint32_t*)(smem + SA_LO + o) = lo;
                acc[mt][nt][0] = 0.f; acc[mt][nt][1] = 0.f;
                acc[mt][nt][2] = 0.f; acc[mt][nt][3] = 0.f;
            }
        }
    }
    __syncthreads();

    // ---- GEMM2 ----
    for (int s = 0; s < 32; s++) {
        if (s < 31) { CP_SUB(g_w2blob + (s + 1) * SUB_BYTES, ((s + 1) & 1) ? SB1 : SB0); }
        CP_COMMIT();
        CP_WAIT1();
        __syncthreads();
        uint32_t sb = (s & 1) ? SB1 : SB0;
        if (!(s & 1)) { A_LOAD(SA_HI, SA_LO, A_STRIDE_B, s >> 1); B_PASS(sb, 2); }
        else          { B_PASS(sb, 1); }
        __syncthreads();
    }

    // ---- scatter epilogue ----
    {
        #pragma unroll
        for (int mt = 0; mt < 2; mt++) {
            int er0 = mb + mt * 16 + g;
            int c0 = scol[er0];
            int c1 = scol[er0 + 8];
            float* p0 = (c0 >= 0) ? (g_sums + (long long)c0 * 256) : nullptr;
            float* p1 = (c1 >= 0) ? (g_sums + (long long)c1 * 256) : nullptr;
            #pragma unroll
            for (int nt = 0; nt < 8; nt++) {
                int cb = nb + nt * 8 + tg * 2;
                float b0 = sbb[cb], b1 = sbb[cb + 1];
                if (p0) red_add_v2(p0 + cb, acc[mt][nt][0] + b0, acc[mt][nt][1] + b1);
                if (p1) red_add_v2(p1 + cb, acc[mt][nt][2] + b0, acc[mt][nt][3] + b1);
            }
        }
    }
}

// ======================================================================
// node kernel: HMMA bf16-3split, 64 nodes / CTA, 256 threads
//   GEMM1: z=[x|mean] (64x384) @ w2a ; GEMM2: elu(H1) (64x256) @ w2b
// ======================================================================
__global__ __launch_bounds__(256, 1)
void node_mma_kernel(const float* __restrict__ x,
                     const float* __restrict__ b2a, const float* __restrict__ b2b,
                     float* __restrict__ out, int N)
{
    extern __shared__ __align__(16) unsigned char smem[];
    const uint32_t sbase = smem_u32(smem);
    const int tid  = threadIdx.x;
    const int lane = tid & 31;
    const int w    = tid >> 5;
    const int g    = lane >> 2;
    const int tg   = lane & 3;
    const int mb   = (w >> 2) * 32;
    const int nb   = (w & 3) * 64;
    const int sel  = lane >> 3;
    const int rin  = lane & 7;

    const int n0 = blockIdx.x * 64;
    const int ncnt = min(64, N - n0);
    float* sba  = (float*)(smem + NB2A);
    float* sbb  = (float*)(smem + NB2B);
    float* sinv = (float*)(smem + NSINV);

    if (tid < 64) {
        float inv = 0.f;
        if (tid < ncnt) inv = 1.0f / (float)max(g_cnt[n0 + tid], 1);
        sinv[tid] = inv;
    }
    if (tid < 256) {
        sba[tid] = b2a[tid];
        sbb[tid] = b2b[tid];
    }
    __syncthreads();

    // ---- load z = [x | mean], split into NA_HI/NA_LO ----
    for (int idx = tid; idx < 64 * 32; idx += 256) {        // x : k = c4*4
        int e = idx >> 5, c4 = idx & 31;
        float4 v = make_float4(0.f, 0.f, 0.f, 0.f);
        if (e < ncnt) v = *(const float4*)(x + (long long)(n0 + e) * 128 + c4 * 4);
        uint32_t h0, l0, h1, l1;
        split2(v.x, v.y, h0, l0);
        split2(v.z, v.w, h1, l1);
        uint32_t off = (uint32_t)e * NA_STRIDE_B + (uint32_t)c4 * 8;
        *(uint2*)(smem + NA_HI + off) = make_uint2(h0, h1);
        *(uint2*)(smem + NA_LO + off) = make_uint2(l0, l1);
    }
    for (int idx = tid; idx < 64 * 64; idx += 256) {        // mean : k = 128 + c4*4
        int e = idx >> 6, c4 = idx & 63;
        float4 v = make_float4(0.f, 0.f, 0.f, 0.f);
        if (e < ncnt) {
            v = *(const float4*)(g_sums + (long long)(n0 + e) * 256 + c4 * 4);
            float inv = sinv[e];
            v.x *= inv; v.y *= inv; v.z *= inv; v.w *= inv;
        }
        uint32_t h0, l0, h1, l1;
        split2(v.x, v.y, h0, l0);
        split2(v.z, v.w, h1, l1);
        uint32_t off = (uint32_t)e * NA_STRIDE_B + 256u + (uint32_t)c4 * 8;
        *(uint2*)(smem + NA_HI + off) = make_uint2(h0, h1);
        *(uint2*)(smem + NA_LO + off) = make_uint2(l0, l1);
    }
    __syncthreads();

    float acc[2][8][4];
    #pragma unroll
    for (int mt = 0; mt < 2; mt++)
        #pragma unroll
        for (int nt = 0; nt < 8; nt++)
            #pragma unroll
            for (int i = 0; i < 4; i++) acc[mt][nt][i] = 0.f;

    uint32_t ahi[2][4], alo[2][4];

    // ---- GEMM1: K=384 -> 48 subchunks ----
    CP_SUB(g_wnablob, NB0);
    CP_COMMIT();
    for (int s = 0; s < 48; s++) {
        if (s < 47) { CP_SUB(g_wnablob + (s + 1) * SUB_BYTES, ((s + 1) & 1) ? NB1 : NB0); }
        else        { CP_SUB(g_wnbblob, NB0); }   // prefetch GEMM2 sub 0 (48 even -> NB0)
        CP_COMMIT();
        CP_WAIT1();
        __syncthreads();
        uint32_t sb = (s & 1) ? NB1 : NB0;
        if (!(s & 1)) { A_LOAD(NA_HI, NA_LO, NA_STRIDE_B, s >> 1); B_PASS(sb, 2); }
        else          { B_PASS(sb, 1); }
        __syncthreads();
    }

    // ---- layer epilogue: bias + ELU + re-split -> overwrite NA (cols 0-255) ----
    {
        #pragma unroll
        for (int mt = 0; mt < 2; mt++) {
            uint32_t r0 = (uint32_t)(mb + mt * 16 + g);
            #pragma unroll
            for (int nt = 0; nt < 8; nt++) {
                int cb = nb + nt * 8 + tg * 2;
                float b0 = sba[cb], b1 = sba[cb + 1];
                float v00 = acc[mt][nt][0] + b0, v01 = acc[mt][nt][1] + b1;
                float v10 = acc[mt][nt][2] + b0, v11 = acc[mt][nt][3] + b1;
                v00 = (v00 > 0.f) ? v00 : expm1f(v00);
                v01 = (v01 > 0.f) ? v01 : expm1f(v01);
                v10 = (v10 > 0.f) ? v10 : expm1f(v10);
                v11 = (v11 > 0.f) ? v11 : expm1f(v11);
                uint32_t hi, lo;
                uint32_t o = r0 * NA_STRIDE_B + (uint32_t)cb * 2;
                split2(v00, v01, hi, lo);
                *(uint32_t*)(smem + NA_HI + o) = hi;
                *(uint32_t*)(smem + NA_LO + o) = lo;
                o += 8 * NA_STRIDE_B;
                split2(v10, v11, hi, lo);
                *(uint32_t*)(smem + NA_HI + o) = hi;
                *(uint32_t*)(smem + NA_LO + o) = lo;
                acc[mt][nt][0] = 0.f; acc[mt][nt][1] = 0.f;
                acc[mt][nt][2] = 0.f; acc[mt][nt][3] = 0.f;
            }
        }
    }
    __syncthreads();

    // ---- GEMM2: K=256 -> 32 subchunks ----
    for (int s = 0; s < 32; s++) {
        if (s < 31) { CP_SUB(g_wnbblob + (s + 1) * SUB_BYTES, ((s + 1) & 1) ? NB1 : NB0); }
        CP_COMMIT();
        CP_WAIT1();
        __syncthreads();
        uint32_t sb = (s & 1) ? NB1 : NB0;
        if (!(s & 1)) { A_LOAD(NA_HI, NA_LO, NA_STRIDE_B, s >> 1); B_PASS(sb, 2); }
        else          { B_PASS(sb, 1); }
        __syncthreads();
    }

    // ---- final epilogue: + b2b -> out ----
    {
        #pragma unroll
        for (int mt = 0; mt < 2; mt++) {
            int r0 = mb + mt * 16 + g;
            int nrow0 = n0 + r0, nrow1 = n0 + r0 + 8;
            #pragma unroll
            for (int nt = 0; nt < 8; nt++) {
                int cb = nb + nt * 8 + tg * 2;
                float b0 = sbb[cb], b1 = sbb[cb + 1];
                if (r0 < ncnt)
                    *(float2*)(out + (long long)nrow0 * 256 + cb) =
                        make_float2(acc[mt][nt][0] + b0, acc[mt][nt][1] + b1);
                if (r0 + 8 < ncnt)
                    *(float2*)(out + (long long)nrow1 * 256 + cb) =
                        make_float2(acc[mt][nt][2] + b0, acc[mt][nt][3] + b1);
            }
        }
    }
}

// ======================================================================
// launch
// ======================================================================
extern "C" void kernel_launch(void* const* d_in, const int* in_sizes, int n_in,
                              void* d_out, int out_size)
{
    const float* x  = (const float*)d_in[0];
    const void*  ei = d_in[1];
    const float* ea = (const float*)d_in[2];
    const float* w1a = (const float*)d_in[5];
    const float* b1a = (const float*)d_in[6];
    const float* w1b = (const float*)d_in[7];
    const float* b1b = (const float*)d_in[8];
    const float* w2a = (const float*)d_in[9];
    const float* b2a = (const float*)d_in[10];
    const float* w2b = (const float*)d_in[11];
    const float* b2b = (const float*)d_in[12];
    float* out = (float*)d_out;

    const int N = in_sizes[0] / 128;
    const int E = in_sizes[1] / 2;

    unsigned char *w1blob = nullptr, *w2blob = nullptr, *wnablob = nullptr, *wnbblob = nullptr;
    cudaGetSymbolAddress((void**)&w1blob, g_w1blob);
    cudaGetSymbolAddress((void**)&w2blob, g_w2blob);
    cudaGetSymbolAddress((void**)&wnablob, g_wnablob);
    cudaGetSymbolAddress((void**)&wnbblob, g_wnbblob);

    cudaFuncSetAttribute(edge_mma_kernel, cudaFuncAttributeMaxDynamicSharedMemorySize, EDGE_SMEM);
    cudaFuncSetAttribute(node_mma_kernel, cudaFuncAttributeMaxDynamicSharedMemorySize, NODE_SMEM);

    detect_idx_kernel<<<1, 256>>>((const int*)ei);
    zero_kernel<<<1024, 256>>>(N);
    prep_weights_kernel<<<128, 512>>>(w1a, w1blob, 256);
    prep_weights_kernel<<<128, 512>>>(w1b, w2blob, 256);
    prep_weights_kernel<<<192, 512>>>(w2a, wnablob, 384);
    prep_weights_kernel<<<128, 512>>>(w2b, wnbblob, 256);
    edge_mma_kernel<<<(E + 63) / 64, 256, EDGE_SMEM>>>(x, ei, ea, b1a, b1b, E, N);
    node_mma_kernel<<<(N + 63) / 64, 256, NODE_SMEM>>>(x, b2a, b2b, out, N);
}